// round 12
// baseline (speedup 1.0000x reference)
#include <cuda_runtime.h>
#include <cuda_fp16.h>
#include <stdint.h>
#include <math.h>

#define D_MODEL     1024
#define EXPERT_DIM  2048
#define NUM_EXPERTS 16
#define SEQ_LEN     2048
#define BATCH       2
#define NTOK        (SEQ_LEN*BATCH)      // 4096 tokens
#define NASSIGN     (NTOK*2)             // 8192 (token, k) assignments

// ---- scratch (static __device__: no allocations allowed) ----
__device__ __half g_Xh[(size_t)NTOK * D_MODEL];                        // 8 MB
__device__ __half g_Hh[(size_t)NASSIGN * EXPERT_DIM];                  // 32 MB
__device__ __half g_W1h[(size_t)NUM_EXPERTS * D_MODEL * EXPERT_DIM];   // 64 MB
__device__ __half g_W2h[(size_t)NUM_EXPERTS * EXPERT_DIM * D_MODEL];   // 64 MB
__device__ int   g_cnt[NUM_EXPERTS];
__device__ int   g_list[NUM_EXPERTS * NTOK];
__device__ float g_rw[NASSIGN];

// ---- prep: zero out, zero counters, convert x -> fp16 (one launch) ----
__global__ void prep_kernel(const float* __restrict__ x,
                            float4* __restrict__ out, int n4, int n8x) {
    int i = blockIdx.x * blockDim.x + threadIdx.x;
    if (i < n4) out[i] = make_float4(0.f, 0.f, 0.f, 0.f);
    if (i < n8x) {
        const float4* in4 = (const float4*)x;
        float4 a = in4[2 * i], b = in4[2 * i + 1];
        __half2 h[4];
        h[0] = __floats2half2_rn(a.x, a.y);
        h[1] = __floats2half2_rn(a.z, a.w);
        h[2] = __floats2half2_rn(b.x, b.y);
        h[3] = __floats2half2_rn(b.z, b.w);
        *(uint4*)(g_Xh + 8 * (size_t)i) = *(uint4*)h;
    }
    if (i < NUM_EXPERTS) g_cnt[i] = 0;
}

// ---- fp32 -> fp16 (RN), 8 elems/thread ----
__global__ void cvt_h_kernel(const float* __restrict__ in, __half* __restrict__ out, int n8) {
    int i = blockIdx.x * blockDim.x + threadIdx.x;
    if (i >= n8) return;
    const float4* in4 = (const float4*)in;
    float4 a = in4[2 * i], b = in4[2 * i + 1];
    __half2 h[4];
    h[0] = __floats2half2_rn(a.x, a.y);
    h[1] = __floats2half2_rn(a.z, a.w);
    h[2] = __floats2half2_rn(b.x, b.y);
    h[3] = __floats2half2_rn(b.z, b.w);
    *(uint4*)(out + 8 * (size_t)i) = *(uint4*)h;
}

// ---- gating: one warp per token (fp32, raw x) ----
__global__ void gate_kernel(const float* __restrict__ x,
                            const float* __restrict__ Wg,
                            const float* __restrict__ bg,
                            const float* __restrict__ bias) {
    int gwarp = (blockIdx.x * blockDim.x + threadIdx.x) >> 5;
    int lane  = threadIdx.x & 31;
    if (gwarp >= NTOK) return;
    const float* xr = x + (size_t)gwarp * D_MODEL;

    float xv[32];
    #pragma unroll
    for (int j = 0; j < 32; j++) xv[j] = xr[lane + 32 * j];

    float logits[NUM_EXPERTS];
    #pragma unroll
    for (int e = 0; e < NUM_EXPERTS; e++) {
        float s = 0.f;
        #pragma unroll
        for (int j = 0; j < 32; j++)
            s += xv[j] * Wg[(size_t)(lane + 32 * j) * NUM_EXPERTS + e];
        #pragma unroll
        for (int o = 16; o; o >>= 1) s += __shfl_xor_sync(0xffffffffu, s, o);
        logits[e] = s + bg[e] + bias[e];
    }

    if (lane == 0) {
        int e0 = 0; float v0 = logits[0];
        #pragma unroll
        for (int e = 1; e < NUM_EXPERTS; e++)
            if (logits[e] > v0) { v0 = logits[e]; e0 = e; }
        int e1 = -1; float v1 = -1e30f;
        #pragma unroll
        for (int e = 0; e < NUM_EXPERTS; e++)
            if (e != e0 && logits[e] > v1) { v1 = logits[e]; e1 = e; }

        float ew1 = __expf(v1 - v0);
        float inv = 1.f / (1.f + ew1);
        g_rw[gwarp * 2 + 0] = inv;
        g_rw[gwarp * 2 + 1] = ew1 * inv;
        int p0 = atomicAdd(&g_cnt[e0], 1);
        g_list[e0 * NTOK + p0] = gwarp * 2 + 0;
        int p1 = atomicAdd(&g_cnt[e1], 1);
        g_list[e1 * NTOK + p1] = gwarp * 2 + 1;
    }
}

// ================= mma / ldmatrix / cp.async helpers =================
__device__ __forceinline__ void mma_f16(float* d, const uint32_t* a, const uint32_t* b) {
    asm volatile(
        "mma.sync.aligned.m16n8k16.row.col.f32.f16.f16.f32 "
        "{%0,%1,%2,%3}, {%4,%5,%6,%7}, {%8,%9}, {%0,%1,%2,%3};\n"
        : "+f"(d[0]), "+f"(d[1]), "+f"(d[2]), "+f"(d[3])
        : "r"(a[0]), "r"(a[1]), "r"(a[2]), "r"(a[3]), "r"(b[0]), "r"(b[1]));
}
__device__ __forceinline__ void ldsm4(uint32_t* r, uint32_t a) {
    asm volatile("ldmatrix.sync.aligned.m8n8.x4.shared.b16 {%0,%1,%2,%3}, [%4];"
        : "=r"(r[0]), "=r"(r[1]), "=r"(r[2]), "=r"(r[3]) : "r"(a));
}
__device__ __forceinline__ void ldsm4t(uint32_t* r, uint32_t a) {
    asm volatile("ldmatrix.sync.aligned.m8n8.x4.trans.shared.b16 {%0,%1,%2,%3}, [%4];"
        : "=r"(r[0]), "=r"(r[1]), "=r"(r[2]), "=r"(r[3]) : "r"(a));
}
__device__ __forceinline__ void cpa16(uint32_t dst, const void* src) {
    asm volatile("cp.async.cg.shared.global [%0], [%1], 16;" :: "r"(dst), "l"(src));
}
#define CPA_COMMIT() asm volatile("cp.async.commit_group;" ::: "memory")
#define CPA_WAIT(n)  asm volatile("cp.async.wait_group %0;" :: "n"(n) : "memory")

// smem layout (5-stage ring, k16/stage, block tile 128m x 128n, fp16):
//   s_entry[128]           @ 0
//   A stages: 5 x 6144 B   @ 512    (A[m][k]: 128 rows x 16 half, stride 48 B)
//   B stages: 5 x 4352 B   @ 31232  (B[k][n]: 16 rows x 128 half, stride 272 B)
#define ASTRB     48
#define BSTRB     272
#define STG       5
#define SM_A      512
#define SM_ASTG   (128 * ASTRB)              // 6144
#define SM_B      (SM_A + STG * SM_ASTG)     // 31232
#define SM_BSTG   (16 * BSTRB)               // 4352
#define SM_TOTAL  (SM_B + STG * SM_BSTG)     // 52992

// 256 threads = 8 warps (4m x 2n), warp tile 32x64; 2 CTAs/SM (independent
// barrier domains overlap each other's sync/wait phases).
template<int K, int N, int KSPLIT, bool FC1>
__global__ __launch_bounds__(256, 2)
void expert_mma(const __half* __restrict__ Wbase,
                const float* __restrict__ BiasBase,
                float* __restrict__ out) {
    extern __shared__ char smem[];
    const int z    = blockIdx.z;
    const int e    = z / KSPLIT;
    const int ks   = z % KSPLIT;
    const int KS   = K / KSPLIT;
    const int koff = ks * KS;
    const int cnt  = g_cnt[e];
    const int m0   = blockIdx.y * 128;
    if (m0 >= cnt) return;
    const int n0   = blockIdx.x * 128;

    const __half* W  = Wbase    + (size_t)e * K * N;
    const float*  bv = BiasBase + (size_t)e * N;

    int* s_entry = (int*)smem;
    const uint32_t sbase = (uint32_t)__cvta_generic_to_shared(smem);

    const int tid = threadIdx.x;
    if (tid < 128) {
        int idx = m0 + tid;
        s_entry[tid] = (idx < cnt) ? g_list[e * NTOK + idx] : -1;
    }
    __syncthreads();

    // ---- producer mappings ----
    // A: 2 threads per row, one 16B chunk each
    const int arow_i = tid >> 1;
    const __half* a_src;
    {
        int en = s_entry[arow_i];
        const __half* base = FC1 ? g_Xh : g_Hh;
        size_t stride      = FC1 ? D_MODEL : EXPERT_DIM;
        size_t row         = (en >= 0) ? (size_t)(FC1 ? (en >> 1) : en) : 0;
        a_src = base + row * stride + koff + (tid & 1) * 8;
    }
    const uint32_t a_dst0 = sbase + SM_A + arow_i * ASTRB + (tid & 1) * 16;
    // B: row = tid>>4 (0..15), chunk = tid&15 (8 halves each)
    const int bkr = tid >> 4;
    const __half* b_src = W + (size_t)(koff + bkr) * N + n0 + (tid & 15) * 8;
    const uint32_t b_dst0 = sbase + SM_B + bkr * BSTRB + (tid & 15) * 16;

    auto produce = [&](int c) {
        int s  = c % STG;
        int k0 = c * 16;
        cpa16(a_dst0 + s * SM_ASTG, a_src + k0);
        cpa16(b_dst0 + s * SM_BSTG, b_src + (size_t)k0 * N);
    };

    // ---- consumer mappings: 8 warps = 4m x 2n, warp tile 32x64 ----
    const int lane = tid & 31;
    const int wid  = tid >> 5;
    const int m0w  = (wid & 3) * 32;
    const int n0w  = (wid >> 2) * 64;
    const int qr   = lane >> 2;
    const int qc   = lane & 3;
    const int l16  = lane & 15;
    const int lhi  = lane >> 4;

    float acc[2][8][4];
    #pragma unroll
    for (int mi = 0; mi < 2; mi++)
        #pragma unroll
        for (int ni = 0; ni < 8; ni++)
            #pragma unroll
            for (int j = 0; j < 4; j++) acc[mi][ni][j] = 0.f;

    const int nst = KS / 16;

    produce(0); CPA_COMMIT();
    produce(1); CPA_COMMIT();
    produce(2); CPA_COMMIT();
    produce(3); CPA_COMMIT();

    for (int c = 0; c < nst; c++) {
        CPA_WAIT(3);
        __syncthreads();

        const uint32_t abase = sbase + SM_A + (c % STG) * SM_ASTG;
        const uint32_t bbase = sbase + SM_B + (c % STG) * SM_BSTG;

        uint32_t af[2][4];
        #pragma unroll
        for (int mi = 0; mi < 2; mi++)
            ldsm4(af[mi], abase + (m0w + mi * 16 + l16) * ASTRB + lhi * 16);
        uint32_t bf[8][2];
        #pragma unroll
        for (int np = 0; np < 4; np++) {
            uint32_t r[4];
            ldsm4t(r, bbase + l16 * BSTRB + (n0w + np * 16 + lhi * 8) * 2);
            bf[np * 2 + 0][0] = r[0]; bf[np * 2 + 0][1] = r[1];
            bf[np * 2 + 1][0] = r[2]; bf[np * 2 + 1][1] = r[3];
        }

        if (c + 4 < nst) produce(c + 4);
        CPA_COMMIT();

        #pragma unroll
        for (int mi = 0; mi < 2; mi++)
            #pragma unroll
            for (int ni = 0; ni < 8; ni++)
                mma_f16(acc[mi][ni], af[mi], bf[ni]);
    }

    // ---- epilogue ----
    #pragma unroll
    for (int mi = 0; mi < 2; mi++) {
        int r0 = m0w + mi * 16 + qr;
        int r1 = r0 + 8;
        int e0 = s_entry[r0];
        int e1 = s_entry[r1];
        #pragma unroll
        for (int ni = 0; ni < 8; ni++) {
            int ncol = n0 + n0w + ni * 8 + qc * 2;
            float bx, by;
            if (KSPLIT > 1 && ks != 0) { bx = 0.f; by = 0.f; }
            else { bx = bv[ncol]; by = bv[ncol + 1]; }
            if (FC1) {
                if (e0 >= 0) {
                    float v0 = acc[mi][ni][0] + bx;
                    float v1 = acc[mi][ni][1] + by;
                    v0 = v0 > 0.f ? v0 : 0.f;
                    v1 = v1 > 0.f ? v1 : 0.f;
                    *(__half2*)(g_Hh + (size_t)e0 * EXPERT_DIM + ncol) =
                        __floats2half2_rn(v0, v1);
                }
                if (e1 >= 0) {
                    float v0 = acc[mi][ni][2] + bx;
                    float v1 = acc[mi][ni][3] + by;
                    v0 = v0 > 0.f ? v0 : 0.f;
                    v1 = v1 > 0.f ? v1 : 0.f;
                    *(__half2*)(g_Hh + (size_t)e1 * EXPERT_DIM + ncol) =
                        __floats2half2_rn(v0, v1);
                }
            } else {
                if (e0 >= 0) {
                    float w = g_rw[e0];
                    float* p = out + (size_t)(e0 >> 1) * D_MODEL + ncol;
                    atomicAdd(p,     w * (acc[mi][ni][0] + bx));
                    atomicAdd(p + 1, w * (acc[mi][ni][1] + by));
                }
                if (e1 >= 0) {
                    float w = g_rw[e1];
                    float* p = out + (size_t)(e1 >> 1) * D_MODEL + ncol;
                    atomicAdd(p,     w * (acc[mi][ni][2] + bx));
                    atomicAdd(p + 1, w * (acc[mi][ni][3] + by));
                }
            }
        }
    }
}

extern "C" void kernel_launch(void* const* d_in, const int* in_sizes, int n_in,
                              void* d_out, int out_size) {
    (void)in_sizes; (void)n_in; (void)out_size;
    const float* x    = (const float*)d_in[0];
    const float* Wg   = (const float*)d_in[1];
    const float* bg   = (const float*)d_in[2];
    const float* bias = (const float*)d_in[3];
    const float* W1   = (const float*)d_in[4];
    const float* b1   = (const float*)d_in[5];
    const float* W2   = (const float*)d_in[6];
    const float* b2   = (const float*)d_in[7];
    float* out = (float*)d_out;

    static int attr_done = 0;
    if (!attr_done) {
        cudaFuncSetAttribute(expert_mma<D_MODEL, EXPERT_DIM, 1, true>,
                             cudaFuncAttributeMaxDynamicSharedMemorySize, SM_TOTAL);
        cudaFuncSetAttribute(expert_mma<EXPERT_DIM, D_MODEL, 2, false>,
                             cudaFuncAttributeMaxDynamicSharedMemorySize, SM_TOTAL);
        attr_done = 1;
    }

    __half *w1h, *w2h;
    cudaGetSymbolAddress((void**)&w1h, g_W1h);
    cudaGetSymbolAddress((void**)&w2h, g_W2h);

    int n4  = NTOK * D_MODEL / 4;   // out zero, float4 units
    int n8x = NTOK * D_MODEL / 8;   // x cvt, 8-elem units
    int n8w = NUM_EXPERTS * D_MODEL * EXPERT_DIM / 8;

    // launch order: FC1 is launch #4 (ncu profiles #4 per rounds 1/2/5/8/11)
    prep_kernel<<<(n4 + 255) / 256, 256>>>(x, (float4*)out, n4, n8x);            // 1
    gate_kernel<<<NTOK / 8, 256>>>(x, Wg, bg, bias);                             // 2
    cvt_h_kernel<<<(n8w + 255) / 256, 256>>>(W1, w1h, n8w);                      // 3
    expert_mma<D_MODEL, EXPERT_DIM, 1, true >                                    // 4 (profiled)
        <<<dim3(EXPERT_DIM / 128, NTOK / 128, NUM_EXPERTS), 256, SM_TOTAL>>>(w1h, b1, out);
    cvt_h_kernel<<<(n8w + 255) / 256, 256>>>(W2, w2h, n8w);                      // 5
    expert_mma<EXPERT_DIM, D_MODEL, 2, false>                                    // 6
        <<<dim3(D_MODEL / 128,  NTOK / 128, NUM_EXPERTS * 2), 256, SM_TOTAL>>>(w2h, b2, out);
}

// round 13
// speedup vs baseline: 1.0996x; 1.0996x over previous
#include <cuda_runtime.h>
#include <cuda_fp16.h>
#include <stdint.h>
#include <math.h>

#define D_MODEL     1024
#define EXPERT_DIM  2048
#define NUM_EXPERTS 16
#define SEQ_LEN     2048
#define BATCH       2
#define NTOK        (SEQ_LEN*BATCH)      // 4096 tokens
#define NASSIGN     (NTOK*2)             // 8192 (token, k) assignments

// ---- scratch (static __device__: no allocations allowed) ----
__device__ __half g_Xh[(size_t)NTOK * D_MODEL];                        // 8 MB
__device__ __half g_Hh[(size_t)NASSIGN * EXPERT_DIM];                  // 32 MB
__device__ __half g_W1h[(size_t)NUM_EXPERTS * D_MODEL * EXPERT_DIM];   // 64 MB
__device__ __half g_W2h[(size_t)NUM_EXPERTS * EXPERT_DIM * D_MODEL];   // 64 MB
__device__ int   g_cnt[NUM_EXPERTS];
__device__ int   g_list[NUM_EXPERTS * NTOK];
__device__ float g_rw[NASSIGN];

// ---- prep: zero out, zero counters, convert x -> fp16 (one launch) ----
__global__ void prep_kernel(const float* __restrict__ x,
                            float4* __restrict__ out, int n4, int n8x) {
    int i = blockIdx.x * blockDim.x + threadIdx.x;
    if (i < n4) out[i] = make_float4(0.f, 0.f, 0.f, 0.f);
    if (i < n8x) {
        const float4* in4 = (const float4*)x;
        float4 a = in4[2 * i], b = in4[2 * i + 1];
        __half2 h[4];
        h[0] = __floats2half2_rn(a.x, a.y);
        h[1] = __floats2half2_rn(a.z, a.w);
        h[2] = __floats2half2_rn(b.x, b.y);
        h[3] = __floats2half2_rn(b.z, b.w);
        *(uint4*)(g_Xh + 8 * (size_t)i) = *(uint4*)h;
    }
    if (i < NUM_EXPERTS) g_cnt[i] = 0;
}

// ---- fp32 -> fp16 (RN), 8 elems/thread ----
__global__ void cvt_h_kernel(const float* __restrict__ in, __half* __restrict__ out, int n8) {
    int i = blockIdx.x * blockDim.x + threadIdx.x;
    if (i >= n8) return;
    const float4* in4 = (const float4*)in;
    float4 a = in4[2 * i], b = in4[2 * i + 1];
    __half2 h[4];
    h[0] = __floats2half2_rn(a.x, a.y);
    h[1] = __floats2half2_rn(a.z, a.w);
    h[2] = __floats2half2_rn(b.x, b.y);
    h[3] = __floats2half2_rn(b.z, b.w);
    *(uint4*)(out + 8 * (size_t)i) = *(uint4*)h;
}

// ---- gating: one warp per token (fp32, raw x) ----
__global__ void gate_kernel(const float* __restrict__ x,
                            const float* __restrict__ Wg,
                            const float* __restrict__ bg,
                            const float* __restrict__ bias) {
    int gwarp = (blockIdx.x * blockDim.x + threadIdx.x) >> 5;
    int lane  = threadIdx.x & 31;
    if (gwarp >= NTOK) return;
    const float* xr = x + (size_t)gwarp * D_MODEL;

    float xv[32];
    #pragma unroll
    for (int j = 0; j < 32; j++) xv[j] = xr[lane + 32 * j];

    float logits[NUM_EXPERTS];
    #pragma unroll
    for (int e = 0; e < NUM_EXPERTS; e++) {
        float s = 0.f;
        #pragma unroll
        for (int j = 0; j < 32; j++)
            s += xv[j] * Wg[(size_t)(lane + 32 * j) * NUM_EXPERTS + e];
        #pragma unroll
        for (int o = 16; o; o >>= 1) s += __shfl_xor_sync(0xffffffffu, s, o);
        logits[e] = s + bg[e] + bias[e];
    }

    if (lane == 0) {
        int e0 = 0; float v0 = logits[0];
        #pragma unroll
        for (int e = 1; e < NUM_EXPERTS; e++)
            if (logits[e] > v0) { v0 = logits[e]; e0 = e; }
        int e1 = -1; float v1 = -1e30f;
        #pragma unroll
        for (int e = 0; e < NUM_EXPERTS; e++)
            if (e != e0 && logits[e] > v1) { v1 = logits[e]; e1 = e; }

        float ew1 = __expf(v1 - v0);
        float inv = 1.f / (1.f + ew1);
        g_rw[gwarp * 2 + 0] = inv;
        g_rw[gwarp * 2 + 1] = ew1 * inv;
        int p0 = atomicAdd(&g_cnt[e0], 1);
        g_list[e0 * NTOK + p0] = gwarp * 2 + 0;
        int p1 = atomicAdd(&g_cnt[e1], 1);
        g_list[e1 * NTOK + p1] = gwarp * 2 + 1;
    }
}

// ================= mma / ldmatrix / cp.async helpers =================
__device__ __forceinline__ void mma_f16(float* d, const uint32_t* a, const uint32_t* b) {
    asm volatile(
        "mma.sync.aligned.m16n8k16.row.col.f32.f16.f16.f32 "
        "{%0,%1,%2,%3}, {%4,%5,%6,%7}, {%8,%9}, {%0,%1,%2,%3};\n"
        : "+f"(d[0]), "+f"(d[1]), "+f"(d[2]), "+f"(d[3])
        : "r"(a[0]), "r"(a[1]), "r"(a[2]), "r"(a[3]), "r"(b[0]), "r"(b[1]));
}
__device__ __forceinline__ void ldsm4(uint32_t* r, uint32_t a) {
    asm volatile("ldmatrix.sync.aligned.m8n8.x4.shared.b16 {%0,%1,%2,%3}, [%4];"
        : "=r"(r[0]), "=r"(r[1]), "=r"(r[2]), "=r"(r[3]) : "r"(a));
}
__device__ __forceinline__ void ldsm4t(uint32_t* r, uint32_t a) {
    asm volatile("ldmatrix.sync.aligned.m8n8.x4.trans.shared.b16 {%0,%1,%2,%3}, [%4];"
        : "=r"(r[0]), "=r"(r[1]), "=r"(r[2]), "=r"(r[3]) : "r"(a));
}
__device__ __forceinline__ void cpa16(uint32_t dst, const void* src) {
    asm volatile("cp.async.cg.shared.global [%0], [%1], 16;" :: "r"(dst), "l"(src));
}
#define CPA_COMMIT() asm volatile("cp.async.commit_group;" ::: "memory")
#define CPA_WAIT(n)  asm volatile("cp.async.wait_group %0;" :: "n"(n) : "memory")

// smem layout (4-stage ring, k32 per stage, block tile 128m x 256n, fp16):
//   s_entry[128]           @ 0
//   A stages: 4 x 10240 B  @ 512    (A[m][k]: 128 rows x 32 half, stride 80 B)
//   B stages: 4 x 16896 B  @ 41472  (B[k][n]: 32 rows x 256 half, stride 528 B)
#define ASTRB     80
#define BSTRB     528
#define STG       4
#define SM_A      512
#define SM_ASTG   (128 * ASTRB)              // 10240
#define SM_B      (SM_A + STG * SM_ASTG)     // 41472
#define SM_BSTG   (32 * BSTRB)               // 16896
#define SM_TOTAL  (SM_B + STG * SM_BSTG)     // 109056

// 512 threads = 16 warps (4m x 4n), warp tile 32x64, 1 CTA/SM.
// Stage = k32: half the waits/barriers of k16, 32 HMMA per sync.
template<int K, int N, int KSPLIT, bool FC1>
__global__ __launch_bounds__(512, 1)
void expert_mma(const __half* __restrict__ Wbase,
                const float* __restrict__ BiasBase,
                float* __restrict__ out) {
    extern __shared__ char smem[];
    const int z    = blockIdx.z;
    const int e    = z / KSPLIT;
    const int ks   = z % KSPLIT;
    const int KS   = K / KSPLIT;
    const int koff = ks * KS;
    const int cnt  = g_cnt[e];
    const int m0   = blockIdx.y * 128;
    if (m0 >= cnt) return;
    const int n0   = blockIdx.x * 256;

    const __half* W  = Wbase    + (size_t)e * K * N;
    const float*  bv = BiasBase + (size_t)e * N;

    int* s_entry = (int*)smem;
    const uint32_t sbase = (uint32_t)__cvta_generic_to_shared(smem);

    const int tid = threadIdx.x;
    if (tid < 128) {
        int idx = m0 + tid;
        s_entry[tid] = (idx < cnt) ? g_list[e * NTOK + idx] : -1;
    }
    __syncthreads();

    // ---- producer mappings (stage = k32) ----
    // A: threads 0..255, 2 per row; each thread 32B (2 chunks) of the k32 slice
    const int arow_i = (tid >> 1) & 127;
    const __half* a_src;
    {
        int en = s_entry[arow_i];
        const __half* base = FC1 ? g_Xh : g_Hh;
        size_t stride      = FC1 ? D_MODEL : EXPERT_DIM;
        size_t row         = (en >= 0) ? (size_t)(FC1 ? (en >> 1) : en) : 0;
        a_src = base + row * stride + koff + (tid & 1) * 16;
    }
    const uint32_t a_dst0 = sbase + SM_A + arow_i * ASTRB + (tid & 1) * 32;
    // B: all 512 threads: row = tid>>4 (0..31), 32B chunk = (tid&15)*16 halves
    const int bkr = tid >> 4;
    const __half* b_src = W + (size_t)(koff + bkr) * N + n0 + (tid & 15) * 16;
    const uint32_t b_dst0 = sbase + SM_B + bkr * BSTRB + (tid & 15) * 32;

    auto produce = [&](int c) {
        int s  = c & (STG - 1);
        int k0 = c * 32;
        if (tid < 256) {
            cpa16(a_dst0 + s * SM_ASTG,      a_src + k0);
            cpa16(a_dst0 + s * SM_ASTG + 16, a_src + k0 + 8);
        }
        const __half* bs = b_src + (size_t)k0 * N;
        uint32_t bo = b_dst0 + s * SM_BSTG;
        cpa16(bo,      bs);
        cpa16(bo + 16, bs + 8);
    };

    // ---- consumer mappings: 16 warps = 4m x 4n, warp tile 32x64 ----
    const int lane = tid & 31;
    const int wid  = tid >> 5;
    const int m0w  = (wid & 3) * 32;
    const int n0w  = (wid >> 2) * 64;
    const int qr   = lane >> 2;
    const int qc   = lane & 3;
    const int l16  = lane & 15;
    const int lhi  = lane >> 4;

    float acc[2][8][4];
    #pragma unroll
    for (int mi = 0; mi < 2; mi++)
        #pragma unroll
        for (int ni = 0; ni < 8; ni++)
            #pragma unroll
            for (int j = 0; j < 4; j++) acc[mi][ni][j] = 0.f;

    uint32_t af[2][4];
    uint32_t bf[8][2];

    auto load_frags = [&](uint32_t abase, uint32_t bbase, int kk) {
        #pragma unroll
        for (int mi = 0; mi < 2; mi++)
            ldsm4(af[mi], abase + (m0w + mi * 16 + l16) * ASTRB + kk * 32 + lhi * 16);
        #pragma unroll
        for (int np = 0; np < 4; np++) {
            uint32_t r[4];
            ldsm4t(r, bbase + (kk * 16 + l16) * BSTRB + (n0w + np * 16 + lhi * 8) * 2);
            bf[np * 2 + 0][0] = r[0]; bf[np * 2 + 0][1] = r[1];
            bf[np * 2 + 1][0] = r[2]; bf[np * 2 + 1][1] = r[3];
        }
    };

    const int nst = KS / 32;

    produce(0); CPA_COMMIT();
    produce(1); CPA_COMMIT();
    produce(2); CPA_COMMIT();

    for (int c = 0; c < nst; c++) {
        CPA_WAIT(2);
        __syncthreads();

        const uint32_t abase = sbase + SM_A + (c & (STG - 1)) * SM_ASTG;
        const uint32_t bbase = sbase + SM_B + (c & (STG - 1)) * SM_BSTG;

        // sub-batch 0: LDSM, then prefetch next stage, then MMA burst
        load_frags(abase, bbase, 0);
        if (c + 3 < nst) produce(c + 3);
        CPA_COMMIT();
        #pragma unroll
        for (int mi = 0; mi < 2; mi++)
            #pragma unroll
            for (int ni = 0; ni < 8; ni++)
                mma_f16(acc[mi][ni], af[mi], bf[ni]);

        // sub-batch 1: LDSM issues while batch-0 MMAs drain
        load_frags(abase, bbase, 1);
        #pragma unroll
        for (int mi = 0; mi < 2; mi++)
            #pragma unroll
            for (int ni = 0; ni < 8; ni++)
                mma_f16(acc[mi][ni], af[mi], bf[ni]);
    }

    // ---- epilogue ----
    #pragma unroll
    for (int mi = 0; mi < 2; mi++) {
        int r0 = m0w + mi * 16 + qr;
        int r1 = r0 + 8;
        int e0 = s_entry[r0];
        int e1 = s_entry[r1];
        #pragma unroll
        for (int ni = 0; ni < 8; ni++) {
            int ncol = n0 + n0w + ni * 8 + qc * 2;
            float bx, by;
            if (KSPLIT > 1 && ks != 0) { bx = 0.f; by = 0.f; }
            else { bx = bv[ncol]; by = bv[ncol + 1]; }
            if (FC1) {
                if (e0 >= 0) {
                    float v0 = acc[mi][ni][0] + bx;
                    float v1 = acc[mi][ni][1] + by;
                    v0 = v0 > 0.f ? v0 : 0.f;
                    v1 = v1 > 0.f ? v1 : 0.f;
                    *(__half2*)(g_Hh + (size_t)e0 * EXPERT_DIM + ncol) =
                        __floats2half2_rn(v0, v1);
                }
                if (e1 >= 0) {
                    float v0 = acc[mi][ni][2] + bx;
                    float v1 = acc[mi][ni][3] + by;
                    v0 = v0 > 0.f ? v0 : 0.f;
                    v1 = v1 > 0.f ? v1 : 0.f;
                    *(__half2*)(g_Hh + (size_t)e1 * EXPERT_DIM + ncol) =
                        __floats2half2_rn(v0, v1);
                }
            } else {
                if (e0 >= 0) {
                    float w = g_rw[e0];
                    float* p = out + (size_t)(e0 >> 1) * D_MODEL + ncol;
                    atomicAdd(p,     w * (acc[mi][ni][0] + bx));
                    atomicAdd(p + 1, w * (acc[mi][ni][1] + by));
                }
                if (e1 >= 0) {
                    float w = g_rw[e1];
                    float* p = out + (size_t)(e1 >> 1) * D_MODEL + ncol;
                    atomicAdd(p,     w * (acc[mi][ni][2] + bx));
                    atomicAdd(p + 1, w * (acc[mi][ni][3] + by));
                }
            }
        }
    }
}

extern "C" void kernel_launch(void* const* d_in, const int* in_sizes, int n_in,
                              void* d_out, int out_size) {
    (void)in_sizes; (void)n_in; (void)out_size;
    const float* x    = (const float*)d_in[0];
    const float* Wg   = (const float*)d_in[1];
    const float* bg   = (const float*)d_in[2];
    const float* bias = (const float*)d_in[3];
    const float* W1   = (const float*)d_in[4];
    const float* b1   = (const float*)d_in[5];
    const float* W2   = (const float*)d_in[6];
    const float* b2   = (const float*)d_in[7];
    float* out = (float*)d_out;

    static int attr_done = 0;
    if (!attr_done) {
        cudaFuncSetAttribute(expert_mma<D_MODEL, EXPERT_DIM, 1, true>,
                             cudaFuncAttributeMaxDynamicSharedMemorySize, SM_TOTAL);
        cudaFuncSetAttribute(expert_mma<EXPERT_DIM, D_MODEL, 2, false>,
                             cudaFuncAttributeMaxDynamicSharedMemorySize, SM_TOTAL);
        attr_done = 1;
    }

    __half *w1h, *w2h;
    cudaGetSymbolAddress((void**)&w1h, g_W1h);
    cudaGetSymbolAddress((void**)&w2h, g_W2h);

    int n4  = NTOK * D_MODEL / 4;
    int n8x = NTOK * D_MODEL / 8;
    int n8w = NUM_EXPERTS * D_MODEL * EXPERT_DIM / 8;

    // launch order: FC1 is launch #4 (ncu profiles launch #4)
    prep_kernel<<<(n4 + 255) / 256, 256>>>(x, (float4*)out, n4, n8x);            // 1
    gate_kernel<<<NTOK / 8, 256>>>(x, Wg, bg, bias);                             // 2
    cvt_h_kernel<<<(n8w + 255) / 256, 256>>>(W1, w1h, n8w);                      // 3
    expert_mma<D_MODEL, EXPERT_DIM, 1, true >                                    // 4 (profiled)
        <<<dim3(EXPERT_DIM / 256, NTOK / 128, NUM_EXPERTS), 512, SM_TOTAL>>>(w1h, b1, out);
    cvt_h_kernel<<<(n8w + 255) / 256, 256>>>(W2, w2h, n8w);                      // 5
    expert_mma<EXPERT_DIM, D_MODEL, 2, false>                                    // 6
        <<<dim3(D_MODEL / 256,  NTOK / 128, NUM_EXPERTS * 2), 512, SM_TOTAL>>>(w2h, b2, out);
}

// round 14
// speedup vs baseline: 1.1555x; 1.0508x over previous
#include <cuda_runtime.h>
#include <cuda_fp16.h>
#include <stdint.h>
#include <math.h>

#define D_MODEL     1024
#define EXPERT_DIM  2048
#define NUM_EXPERTS 16
#define SEQ_LEN     2048
#define BATCH       2
#define NTOK        (SEQ_LEN*BATCH)      // 4096 tokens
#define NASSIGN     (NTOK*2)             // 8192 (token, k) assignments

// ---- scratch (static __device__: no allocations allowed) ----
__device__ __half g_Xh[(size_t)NTOK * D_MODEL];                        // 8 MB
__device__ __half g_Hh[(size_t)NASSIGN * EXPERT_DIM];                  // 32 MB
__device__ __half g_W1h[(size_t)NUM_EXPERTS * D_MODEL * EXPERT_DIM];   // 64 MB
__device__ __half g_W2h[(size_t)NUM_EXPERTS * EXPERT_DIM * D_MODEL];   // 64 MB
__device__ int   g_cnt[NUM_EXPERTS];
__device__ int   g_list[NUM_EXPERTS * NTOK];
__device__ float g_rw[NASSIGN];

// ---- mega-prep: zero out, zero counters, cvt x/W1/W2 -> fp16 (ONE launch) ----
__global__ void prep_kernel(const float* __restrict__ x,
                            const float* __restrict__ W1,
                            const float* __restrict__ W2,
                            float4* __restrict__ out,
                            int n4, int n8x, int n8w) {
    int i = blockIdx.x * blockDim.x + threadIdx.x;
    if (i < n4) out[i] = make_float4(0.f, 0.f, 0.f, 0.f);
    if (i < n8x) {
        const float4* in4 = (const float4*)x;
        float4 a = in4[2 * i], b = in4[2 * i + 1];
        __half2 h[4];
        h[0] = __floats2half2_rn(a.x, a.y);
        h[1] = __floats2half2_rn(a.z, a.w);
        h[2] = __floats2half2_rn(b.x, b.y);
        h[3] = __floats2half2_rn(b.z, b.w);
        *(uint4*)(g_Xh + 8 * (size_t)i) = *(uint4*)h;
    }
    if (i < n8w) {
        {
            const float4* in4 = (const float4*)W1;
            float4 a = in4[2 * i], b = in4[2 * i + 1];
            __half2 h[4];
            h[0] = __floats2half2_rn(a.x, a.y);
            h[1] = __floats2half2_rn(a.z, a.w);
            h[2] = __floats2half2_rn(b.x, b.y);
            h[3] = __floats2half2_rn(b.z, b.w);
            *(uint4*)(g_W1h + 8 * (size_t)i) = *(uint4*)h;
        }
        {
            const float4* in4 = (const float4*)W2;
            float4 a = in4[2 * i], b = in4[2 * i + 1];
            __half2 h[4];
            h[0] = __floats2half2_rn(a.x, a.y);
            h[1] = __floats2half2_rn(a.z, a.w);
            h[2] = __floats2half2_rn(b.x, b.y);
            h[3] = __floats2half2_rn(b.z, b.w);
            *(uint4*)(g_W2h + 8 * (size_t)i) = *(uint4*)h;
        }
    }
    if (i < NUM_EXPERTS) g_cnt[i] = 0;
}

// ---- gating: one warp per token (fp32, raw x) ----
__global__ void gate_kernel(const float* __restrict__ x,
                            const float* __restrict__ Wg,
                            const float* __restrict__ bg,
                            const float* __restrict__ bias) {
    int gwarp = (blockIdx.x * blockDim.x + threadIdx.x) >> 5;
    int lane  = threadIdx.x & 31;
    if (gwarp >= NTOK) return;
    const float* xr = x + (size_t)gwarp * D_MODEL;

    float xv[32];
    #pragma unroll
    for (int j = 0; j < 32; j++) xv[j] = xr[lane + 32 * j];

    float logits[NUM_EXPERTS];
    #pragma unroll
    for (int e = 0; e < NUM_EXPERTS; e++) {
        float s = 0.f;
        #pragma unroll
        for (int j = 0; j < 32; j++)
            s += xv[j] * Wg[(size_t)(lane + 32 * j) * NUM_EXPERTS + e];
        #pragma unroll
        for (int o = 16; o; o >>= 1) s += __shfl_xor_sync(0xffffffffu, s, o);
        logits[e] = s + bg[e] + bias[e];
    }

    if (lane == 0) {
        int e0 = 0; float v0 = logits[0];
        #pragma unroll
        for (int e = 1; e < NUM_EXPERTS; e++)
            if (logits[e] > v0) { v0 = logits[e]; e0 = e; }
        int e1 = -1; float v1 = -1e30f;
        #pragma unroll
        for (int e = 0; e < NUM_EXPERTS; e++)
            if (e != e0 && logits[e] > v1) { v1 = logits[e]; e1 = e; }

        float ew1 = __expf(v1 - v0);
        float inv = 1.f / (1.f + ew1);
        g_rw[gwarp * 2 + 0] = inv;
        g_rw[gwarp * 2 + 1] = ew1 * inv;
        int p0 = atomicAdd(&g_cnt[e0], 1);
        g_list[e0 * NTOK + p0] = gwarp * 2 + 0;
        int p1 = atomicAdd(&g_cnt[e1], 1);
        g_list[e1 * NTOK + p1] = gwarp * 2 + 1;
    }
}

// ================= mma / ldmatrix / cp.async helpers =================
__device__ __forceinline__ void mma_f16(float* d, const uint32_t* a, const uint32_t* b) {
    asm volatile(
        "mma.sync.aligned.m16n8k16.row.col.f32.f16.f16.f32 "
        "{%0,%1,%2,%3}, {%4,%5,%6,%7}, {%8,%9}, {%0,%1,%2,%3};\n"
        : "+f"(d[0]), "+f"(d[1]), "+f"(d[2]), "+f"(d[3])
        : "r"(a[0]), "r"(a[1]), "r"(a[2]), "r"(a[3]), "r"(b[0]), "r"(b[1]));
}
__device__ __forceinline__ void ldsm4(uint32_t* r, uint32_t a) {
    asm volatile("ldmatrix.sync.aligned.m8n8.x4.shared.b16 {%0,%1,%2,%3}, [%4];"
        : "=r"(r[0]), "=r"(r[1]), "=r"(r[2]), "=r"(r[3]) : "r"(a));
}
__device__ __forceinline__ void ldsm4t(uint32_t* r, uint32_t a) {
    asm volatile("ldmatrix.sync.aligned.m8n8.x4.trans.shared.b16 {%0,%1,%2,%3}, [%4];"
        : "=r"(r[0]), "=r"(r[1]), "=r"(r[2]), "=r"(r[3]) : "r"(a));
}
__device__ __forceinline__ void cpa16(uint32_t dst, const void* src) {
    asm volatile("cp.async.cg.shared.global [%0], [%1], 16;" :: "r"(dst), "l"(src));
}
#define CPA_COMMIT() asm volatile("cp.async.commit_group;" ::: "memory")

// Unified GEMM: 512 threads = 16 warps (4m x 4n), warp tile 32x64, 1 CTA/SM.
// Block tile 128m x 256n. Stage depth SK (16 or 32), NSTG-deep cp.async ring.
// FC1: SK=32/NSTG=4 (fewer barriers; measured faster for FC1)
// FC2: SK=16/NSTG=5 (round-8 proven config)
template<int K, int N, int KSPLIT, int SK, int NSTG, bool FC1>
__global__ __launch_bounds__(512, 1)
void expert_mma(const __half* __restrict__ Wbase,
                const float* __restrict__ BiasBase,
                float* __restrict__ out) {
    extern __shared__ char smem[];
    constexpr int ASTRB   = SK * 2 + 16;      // A row stride bytes (48 / 80)
    constexpr int BSTRB   = 528;              // B k-row stride bytes
    constexpr int SM_ASTG = 128 * ASTRB;
    constexpr int SM_BSTG = SK * BSTRB;
    constexpr int SM_AOFF = 512;
    constexpr int SM_BOFF = SM_AOFF + NSTG * SM_ASTG;

    const int z    = blockIdx.z;
    const int e    = z / KSPLIT;
    const int ks   = z % KSPLIT;
    const int KS   = K / KSPLIT;
    const int koff = ks * KS;
    const int cnt  = g_cnt[e];
    const int m0   = blockIdx.y * 128;
    if (m0 >= cnt) return;
    const int n0   = blockIdx.x * 256;

    const __half* W  = Wbase    + (size_t)e * K * N;
    const float*  bv = BiasBase + (size_t)e * N;

    int* s_entry = (int*)smem;
    const uint32_t sbase = (uint32_t)__cvta_generic_to_shared(smem);

    const int tid = threadIdx.x;
    if (tid < 128) {
        int idx = m0 + tid;
        s_entry[tid] = (idx < cnt) ? g_list[e * NTOK + idx] : -1;
    }
    __syncthreads();

    // ---- producer mappings ----
    // A: threads 0..255, 2 per row; each thread SK/2 halves (SK/16 x 16B chunks)
    const int arow_i = (tid >> 1) & 127;
    const __half* a_src;
    {
        int en = s_entry[arow_i];
        const __half* base = FC1 ? g_Xh : g_Hh;
        size_t stride      = FC1 ? D_MODEL : EXPERT_DIM;
        size_t row         = (en >= 0) ? (size_t)(FC1 ? (en >> 1) : en) : 0;
        a_src = base + row * stride + koff + (tid & 1) * (SK / 2);
    }
    const uint32_t a_dst0 = sbase + SM_AOFF + arow_i * ASTRB + (tid & 1) * SK;
    // B: 512/SK threads per k-row; each thread SK/2 halves (SK/16 chunks)
    constexpr int TPR = 512 / SK;             // threads per B k-row
    const int bkr = tid / TPR;                // 0..SK-1
    const int bln = tid % TPR;
    const __half* b_src = W + (size_t)(koff + bkr) * N + n0 + bln * (SK / 2);
    const uint32_t b_dst0 = sbase + SM_BOFF + bkr * BSTRB + bln * SK;

    auto produce = [&](int c) {
        int s  = c % NSTG;
        int k0 = c * SK;
        if (tid < 256) {
            cpa16(a_dst0 + s * SM_ASTG, a_src + k0);
            if (SK == 32) cpa16(a_dst0 + s * SM_ASTG + 16, a_src + k0 + 8);
        }
        const __half* bs = b_src + (size_t)k0 * N;
        uint32_t bo = b_dst0 + s * SM_BSTG;
        cpa16(bo, bs);
        if (SK == 32) cpa16(bo + 16, bs + 8);
    };

    // ---- consumer mappings: 16 warps = 4m x 4n, warp tile 32x64 ----
    const int lane = tid & 31;
    const int wid  = tid >> 5;
    const int m0w  = (wid & 3) * 32;
    const int n0w  = (wid >> 2) * 64;
    const int qr   = lane >> 2;
    const int qc   = lane & 3;
    const int l16  = lane & 15;
    const int lhi  = lane >> 4;

    float acc[2][8][4];
    #pragma unroll
    for (int mi = 0; mi < 2; mi++)
        #pragma unroll
        for (int ni = 0; ni < 8; ni++)
            #pragma unroll
            for (int j = 0; j < 4; j++) acc[mi][ni][j] = 0.f;

    uint32_t af[2][4];
    uint32_t bf[8][2];

    auto load_frags = [&](uint32_t abase, uint32_t bbase, int kk) {
        #pragma unroll
        for (int mi = 0; mi < 2; mi++)
            ldsm4(af[mi], abase + (m0w + mi * 16 + l16) * ASTRB + kk * 32 + lhi * 16);
        #pragma unroll
        for (int np = 0; np < 4; np++) {
            uint32_t r[4];
            ldsm4t(r, bbase + (kk * 16 + l16) * BSTRB + (n0w + np * 16 + lhi * 8) * 2);
            bf[np * 2 + 0][0] = r[0]; bf[np * 2 + 0][1] = r[1];
            bf[np * 2 + 1][0] = r[2]; bf[np * 2 + 1][1] = r[3];
        }
    };

    const int nst = KS / SK;

    #pragma unroll
    for (int c = 0; c < NSTG - 1; c++) { produce(c); CPA_COMMIT(); }

    for (int c = 0; c < nst; c++) {
        asm volatile("cp.async.wait_group %0;" :: "n"(NSTG - 2) : "memory");
        __syncthreads();

        const uint32_t abase = sbase + SM_AOFF + (c % NSTG) * SM_ASTG;
        const uint32_t bbase = sbase + SM_BOFF + (c % NSTG) * SM_BSTG;

        #pragma unroll
        for (int kk = 0; kk < SK / 16; kk++) {
            load_frags(abase, bbase, kk);
            if (kk == 0) {
                if (c + NSTG - 1 < nst) produce(c + NSTG - 1);
                CPA_COMMIT();
            }
            #pragma unroll
            for (int mi = 0; mi < 2; mi++)
                #pragma unroll
                for (int ni = 0; ni < 8; ni++)
                    mma_f16(acc[mi][ni], af[mi], bf[ni]);
        }
    }

    // ---- epilogue ----
    #pragma unroll
    for (int mi = 0; mi < 2; mi++) {
        int r0 = m0w + mi * 16 + qr;
        int r1 = r0 + 8;
        int e0 = s_entry[r0];
        int e1 = s_entry[r1];
        #pragma unroll
        for (int ni = 0; ni < 8; ni++) {
            int ncol = n0 + n0w + ni * 8 + qc * 2;
            float bx, by;
            if (KSPLIT > 1 && ks != 0) { bx = 0.f; by = 0.f; }
            else { bx = bv[ncol]; by = bv[ncol + 1]; }
            if (FC1) {
                if (e0 >= 0) {
                    float v0 = acc[mi][ni][0] + bx;
                    float v1 = acc[mi][ni][1] + by;
                    v0 = v0 > 0.f ? v0 : 0.f;
                    v1 = v1 > 0.f ? v1 : 0.f;
                    *(__half2*)(g_Hh + (size_t)e0 * EXPERT_DIM + ncol) =
                        __floats2half2_rn(v0, v1);
                }
                if (e1 >= 0) {
                    float v0 = acc[mi][ni][2] + bx;
                    float v1 = acc[mi][ni][3] + by;
                    v0 = v0 > 0.f ? v0 : 0.f;
                    v1 = v1 > 0.f ? v1 : 0.f;
                    *(__half2*)(g_Hh + (size_t)e1 * EXPERT_DIM + ncol) =
                        __floats2half2_rn(v0, v1);
                }
            } else {
                if (e0 >= 0) {
                    float w = g_rw[e0];
                    float* p = out + (size_t)(e0 >> 1) * D_MODEL + ncol;
                    atomicAdd(p,     w * (acc[mi][ni][0] + bx));
                    atomicAdd(p + 1, w * (acc[mi][ni][1] + by));
                }
                if (e1 >= 0) {
                    float w = g_rw[e1];
                    float* p = out + (size_t)(e1 >> 1) * D_MODEL + ncol;
                    atomicAdd(p,     w * (acc[mi][ni][2] + bx));
                    atomicAdd(p + 1, w * (acc[mi][ni][3] + by));
                }
            }
        }
    }
}

// FC1: SK=32, NSTG=4 -> smem 512 + 4*10240 + 4*16896 = 109056
// FC2: SK=16, NSTG=5 -> smem 512 + 5*6144  + 5*8448  = 73472
#define SMT_FC1 109056
#define SMT_FC2 73472

extern "C" void kernel_launch(void* const* d_in, const int* in_sizes, int n_in,
                              void* d_out, int out_size) {
    (void)in_sizes; (void)n_in; (void)out_size;
    const float* x    = (const float*)d_in[0];
    const float* Wg   = (const float*)d_in[1];
    const float* bg   = (const float*)d_in[2];
    const float* bias = (const float*)d_in[3];
    const float* W1   = (const float*)d_in[4];
    const float* b1   = (const float*)d_in[5];
    const float* W2   = (const float*)d_in[6];
    const float* b2   = (const float*)d_in[7];
    float* out = (float*)d_out;

    static int attr_done = 0;
    if (!attr_done) {
        cudaFuncSetAttribute(expert_mma<D_MODEL, EXPERT_DIM, 1, 32, 4, true>,
                             cudaFuncAttributeMaxDynamicSharedMemorySize, SMT_FC1);
        cudaFuncSetAttribute(expert_mma<EXPERT_DIM, D_MODEL, 2, 16, 5, false>,
                             cudaFuncAttributeMaxDynamicSharedMemorySize, SMT_FC2);
        attr_done = 1;
    }

    __half *w1h, *w2h;
    cudaGetSymbolAddress((void**)&w1h, g_W1h);
    cudaGetSymbolAddress((void**)&w2h, g_W2h);

    int n4  = NTOK * D_MODEL / 4;
    int n8x = NTOK * D_MODEL / 8;
    int n8w = NUM_EXPERTS * D_MODEL * EXPERT_DIM / 8;

    // launch order: FC2 is launch #4 (ncu profiles launch #4)
    prep_kernel<<<(n8w + 255) / 256, 256>>>(x, W1, W2, (float4*)out,
                                            n4, n8x, n8w);                       // 1
    gate_kernel<<<NTOK / 8, 256>>>(x, Wg, bg, bias);                             // 2
    expert_mma<D_MODEL, EXPERT_DIM, 1, 32, 4, true >                             // 3
        <<<dim3(EXPERT_DIM / 256, NTOK / 128, NUM_EXPERTS), 512, SMT_FC1>>>(w1h, b1, out);
    expert_mma<EXPERT_DIM, D_MODEL, 2, 16, 5, false>                             // 4 (profiled)
        <<<dim3(D_MODEL / 256,  NTOK / 128, NUM_EXPERTS * 2), 512, SMT_FC2>>>(w2h, b2, out);
}

// round 15
// speedup vs baseline: 1.1896x; 1.0295x over previous
#include <cuda_runtime.h>
#include <cuda_fp16.h>
#include <stdint.h>
#include <math.h>

#define D_MODEL     1024
#define EXPERT_DIM  2048
#define NUM_EXPERTS 16
#define SEQ_LEN     2048
#define BATCH       2
#define NTOK        (SEQ_LEN*BATCH)      // 4096 tokens
#define NASSIGN     (NTOK*2)             // 8192 (token, k) assignments

// ---- scratch (static __device__: no allocations allowed) ----
__device__ __half g_Xh[(size_t)NTOK * D_MODEL];                        // 8 MB
__device__ __half g_Hh[(size_t)NASSIGN * EXPERT_DIM];                  // 32 MB
__device__ __half g_W1h[(size_t)NUM_EXPERTS * D_MODEL * EXPERT_DIM];   // 64 MB
__device__ __half g_W2h[(size_t)NUM_EXPERTS * EXPERT_DIM * D_MODEL];   // 64 MB
__device__ int   g_cnt[NUM_EXPERTS];
__device__ int   g_list[NUM_EXPERTS * NTOK];
__device__ float g_rw[NASSIGN];

// ---- prep_misc: zero out, zero counters, cvt x -> fp16 ----
__global__ void prep_misc_kernel(const float* __restrict__ x,
                                 float4* __restrict__ out, int n4, int n8x) {
    int i = blockIdx.x * blockDim.x + threadIdx.x;
    if (i < n4) out[i] = make_float4(0.f, 0.f, 0.f, 0.f);
    if (i < n8x) {
        const float4* in4 = (const float4*)x;
        float4 a = in4[2 * i], b = in4[2 * i + 1];
        __half2 h[4];
        h[0] = __floats2half2_rn(a.x, a.y);
        h[1] = __floats2half2_rn(a.z, a.w);
        h[2] = __floats2half2_rn(b.x, b.y);
        h[3] = __floats2half2_rn(b.z, b.w);
        *(uint4*)(g_Xh + 8 * (size_t)i) = *(uint4*)h;
    }
    if (i < NUM_EXPERTS) g_cnt[i] = 0;
}

// ---- prep_w: cvt W1 and W2 -> fp16 (one launch) ----
__global__ void prep_w_kernel(const float* __restrict__ W1,
                              const float* __restrict__ W2, int n8w) {
    int i = blockIdx.x * blockDim.x + threadIdx.x;
    if (i >= n8w) return;
    {
        const float4* in4 = (const float4*)W1;
        float4 a = in4[2 * i], b = in4[2 * i + 1];
        __half2 h[4];
        h[0] = __floats2half2_rn(a.x, a.y);
        h[1] = __floats2half2_rn(a.z, a.w);
        h[2] = __floats2half2_rn(b.x, b.y);
        h[3] = __floats2half2_rn(b.z, b.w);
        *(uint4*)(g_W1h + 8 * (size_t)i) = *(uint4*)h;
    }
    {
        const float4* in4 = (const float4*)W2;
        float4 a = in4[2 * i], b = in4[2 * i + 1];
        __half2 h[4];
        h[0] = __floats2half2_rn(a.x, a.y);
        h[1] = __floats2half2_rn(a.z, a.w);
        h[2] = __floats2half2_rn(b.x, b.y);
        h[3] = __floats2half2_rn(b.z, b.w);
        *(uint4*)(g_W2h + 8 * (size_t)i) = *(uint4*)h;
    }
}

// ---- gating: one warp per token (fp32, raw x) ----
__global__ void gate_kernel(const float* __restrict__ x,
                            const float* __restrict__ Wg,
                            const float* __restrict__ bg,
                            const float* __restrict__ bias) {
    int gwarp = (blockIdx.x * blockDim.x + threadIdx.x) >> 5;
    int lane  = threadIdx.x & 31;
    if (gwarp >= NTOK) return;
    const float* xr = x + (size_t)gwarp * D_MODEL;

    float xv[32];
    #pragma unroll
    for (int j = 0; j < 32; j++) xv[j] = xr[lane + 32 * j];

    float logits[NUM_EXPERTS];
    #pragma unroll
    for (int e = 0; e < NUM_EXPERTS; e++) {
        float s = 0.f;
        #pragma unroll
        for (int j = 0; j < 32; j++)
            s += xv[j] * Wg[(size_t)(lane + 32 * j) * NUM_EXPERTS + e];
        #pragma unroll
        for (int o = 16; o; o >>= 1) s += __shfl_xor_sync(0xffffffffu, s, o);
        logits[e] = s + bg[e] + bias[e];
    }

    if (lane == 0) {
        int e0 = 0; float v0 = logits[0];
        #pragma unroll
        for (int e = 1; e < NUM_EXPERTS; e++)
            if (logits[e] > v0) { v0 = logits[e]; e0 = e; }
        int e1 = -1; float v1 = -1e30f;
        #pragma unroll
        for (int e = 0; e < NUM_EXPERTS; e++)
            if (e != e0 && logits[e] > v1) { v1 = logits[e]; e1 = e; }

        float ew1 = __expf(v1 - v0);
        float inv = 1.f / (1.f + ew1);
        g_rw[gwarp * 2 + 0] = inv;
        g_rw[gwarp * 2 + 1] = ew1 * inv;
        int p0 = atomicAdd(&g_cnt[e0], 1);
        g_list[e0 * NTOK + p0] = gwarp * 2 + 0;
        int p1 = atomicAdd(&g_cnt[e1], 1);
        g_list[e1 * NTOK + p1] = gwarp * 2 + 1;
    }
}

// ================= mma / ldmatrix / cp.async helpers =================
__device__ __forceinline__ void mma_f16(float* d, const uint32_t* a, const uint32_t* b) {
    asm volatile(
        "mma.sync.aligned.m16n8k16.row.col.f32.f16.f16.f32 "
        "{%0,%1,%2,%3}, {%4,%5,%6,%7}, {%8,%9}, {%0,%1,%2,%3};\n"
        : "+f"(d[0]), "+f"(d[1]), "+f"(d[2]), "+f"(d[3])
        : "r"(a[0]), "r"(a[1]), "r"(a[2]), "r"(a[3]), "r"(b[0]), "r"(b[1]));
}
__device__ __forceinline__ void ldsm4(uint32_t* r, uint32_t a) {
    asm volatile("ldmatrix.sync.aligned.m8n8.x4.shared.b16 {%0,%1,%2,%3}, [%4];"
        : "=r"(r[0]), "=r"(r[1]), "=r"(r[2]), "=r"(r[3]) : "r"(a));
}
__device__ __forceinline__ void ldsm4t(uint32_t* r, uint32_t a) {
    asm volatile("ldmatrix.sync.aligned.m8n8.x4.trans.shared.b16 {%0,%1,%2,%3}, [%4];"
        : "=r"(r[0]), "=r"(r[1]), "=r"(r[2]), "=r"(r[3]) : "r"(a));
}
__device__ __forceinline__ void cpa16(uint32_t dst, const void* src) {
    asm volatile("cp.async.cg.shared.global [%0], [%1], 16;" :: "r"(dst), "l"(src));
}
#define CPA_COMMIT() asm volatile("cp.async.commit_group;" ::: "memory")
#define CPA_WAIT(n)  asm volatile("cp.async.wait_group %0;" :: "n"(n) : "memory")

// smem layout (5-stage ring, k16/stage, block tile 128m x 256n, fp16):
//   s_entry[128]           @ 0
//   A stages: 5 x 6144 B   @ 512    (A[m][k]: 128 rows x 16 half, stride 48 B)
//   B stages: 5 x 8448 B   @ 31232  (B[k][n]: 16 rows x 256 half, stride 528 B)
#define ASTRB     48
#define BSTRB     528
#define STG       5
#define SM_A      512
#define SM_ASTG   (128 * ASTRB)              // 6144
#define SM_B      (SM_A + STG * SM_ASTG)     // 31232
#define SM_BSTG   (16 * BSTRB)               // 8448
#define SM_TOTAL  (SM_B + STG * SM_BSTG)     // 73472

// 512 threads = 16 warps (4m x 4n), warp tile 32x64, 1 CTA/SM. (round-8 proven)
template<int K, int N, int KSPLIT, bool FC1>
__global__ __launch_bounds__(512, 1)
void expert_mma(const __half* __restrict__ Wbase,
                const float* __restrict__ BiasBase,
                float* __restrict__ out) {
    extern __shared__ char smem[];
    const int z    = blockIdx.z;
    const int e    = z / KSPLIT;
    const int ks   = z % KSPLIT;
    const int KS   = K / KSPLIT;
    const int koff = ks * KS;
    const int cnt  = g_cnt[e];
    const int m0   = blockIdx.y * 128;
    if (m0 >= cnt) return;
    const int n0   = blockIdx.x * 256;

    const __half* W  = Wbase    + (size_t)e * K * N;
    const float*  bv = BiasBase + (size_t)e * N;

    int* s_entry = (int*)smem;
    const uint32_t sbase = (uint32_t)__cvta_generic_to_shared(smem);

    const int tid = threadIdx.x;
    if (tid < 128) {
        int idx = m0 + tid;
        s_entry[tid] = (idx < cnt) ? g_list[e * NTOK + idx] : -1;
    }
    __syncthreads();

    // ---- producer mappings ----
    // A: threads 0..255, 2 per row, one 16B chunk each
    const int arow_i = (tid >> 1) & 127;
    const __half* a_src;
    {
        int en = s_entry[arow_i];
        const __half* base = FC1 ? g_Xh : g_Hh;
        size_t stride      = FC1 ? D_MODEL : EXPERT_DIM;
        size_t row         = (en >= 0) ? (size_t)(FC1 ? (en >> 1) : en) : 0;
        a_src = base + row * stride + koff + (tid & 1) * 8;
    }
    const uint32_t a_dst0 = sbase + SM_A + arow_i * ASTRB + (tid & 1) * 16;
    // B: all 512 threads, one 16B chunk: row = tid>>5 (0..15), chunk = tid&31
    const int bkr = tid >> 5;
    const __half* b_src = W + (size_t)(koff + bkr) * N + n0 + (tid & 31) * 8;
    const uint32_t b_dst0 = sbase + SM_B + bkr * BSTRB + (tid & 31) * 16;

    auto produce = [&](int c) {
        int s  = c % STG;
        int k0 = c * 16;
        if (tid < 256) cpa16(a_dst0 + s * SM_ASTG, a_src + k0);
        cpa16(b_dst0 + s * SM_BSTG, b_src + (size_t)k0 * N);
    };

    // ---- consumer mappings: 16 warps = 4m x 4n, warp tile 32x64 ----
    const int lane = tid & 31;
    const int wid  = tid >> 5;
    const int m0w  = (wid & 3) * 32;
    const int n0w  = (wid >> 2) * 64;
    const int qr   = lane >> 2;
    const int qc   = lane & 3;
    const int l16  = lane & 15;
    const int lhi  = lane >> 4;

    float acc[2][8][4];
    #pragma unroll
    for (int mi = 0; mi < 2; mi++)
        #pragma unroll
        for (int ni = 0; ni < 8; ni++)
            #pragma unroll
            for (int j = 0; j < 4; j++) acc[mi][ni][j] = 0.f;

    const int nst = KS / 16;

    produce(0); CPA_COMMIT();
    produce(1); CPA_COMMIT();
    produce(2); CPA_COMMIT();
    produce(3); CPA_COMMIT();

    for (int c = 0; c < nst; c++) {
        CPA_WAIT(3);
        __syncthreads();

        const uint32_t abase = sbase + SM_A + (c % STG) * SM_ASTG;
        const uint32_t bbase = sbase + SM_B + (c % STG) * SM_BSTG;

        uint32_t af[2][4];
        #pragma unroll
        for (int mi = 0; mi < 2; mi++)
            ldsm4(af[mi], abase + (m0w + mi * 16 + l16) * ASTRB + lhi * 16);
        uint32_t bf[8][2];
        #pragma unroll
        for (int np = 0; np < 4; np++) {
            uint32_t r[4];
            ldsm4t(r, bbase + l16 * BSTRB + (n0w + np * 16 + lhi * 8) * 2);
            bf[np * 2 + 0][0] = r[0]; bf[np * 2 + 0][1] = r[1];
            bf[np * 2 + 1][0] = r[2]; bf[np * 2 + 1][1] = r[3];
        }

        if (c + 4 < nst) produce(c + 4);
        CPA_COMMIT();

        #pragma unroll
        for (int mi = 0; mi < 2; mi++)
            #pragma unroll
            for (int ni = 0; ni < 8; ni++)
                mma_f16(acc[mi][ni], af[mi], bf[ni]);
    }

    // ---- epilogue ----
    #pragma unroll
    for (int mi = 0; mi < 2; mi++) {
        int r0 = m0w + mi * 16 + qr;
        int r1 = r0 + 8;
        int e0 = s_entry[r0];
        int e1 = s_entry[r1];
        #pragma unroll
        for (int ni = 0; ni < 8; ni++) {
            int ncol = n0 + n0w + ni * 8 + qc * 2;
            float bx, by;
            if (KSPLIT > 1 && ks != 0) { bx = 0.f; by = 0.f; }
            else { bx = bv[ncol]; by = bv[ncol + 1]; }
            if (FC1) {
                if (e0 >= 0) {
                    float v0 = acc[mi][ni][0] + bx;
                    float v1 = acc[mi][ni][1] + by;
                    v0 = v0 > 0.f ? v0 : 0.f;
                    v1 = v1 > 0.f ? v1 : 0.f;
                    *(__half2*)(g_Hh + (size_t)e0 * EXPERT_DIM + ncol) =
                        __floats2half2_rn(v0, v1);
                }
                if (e1 >= 0) {
                    float v0 = acc[mi][ni][2] + bx;
                    float v1 = acc[mi][ni][3] + by;
                    v0 = v0 > 0.f ? v0 : 0.f;
                    v1 = v1 > 0.f ? v1 : 0.f;
                    *(__half2*)(g_Hh + (size_t)e1 * EXPERT_DIM + ncol) =
                        __floats2half2_rn(v0, v1);
                }
            } else {
                if (e0 >= 0) {
                    float w = g_rw[e0];
                    float* p = out + (size_t)(e0 >> 1) * D_MODEL + ncol;
                    atomicAdd(p,     w * (acc[mi][ni][0] + bx));
                    atomicAdd(p + 1, w * (acc[mi][ni][1] + by));
                }
                if (e1 >= 0) {
                    float w = g_rw[e1];
                    float* p = out + (size_t)(e1 >> 1) * D_MODEL + ncol;
                    atomicAdd(p,     w * (acc[mi][ni][2] + bx));
                    atomicAdd(p + 1, w * (acc[mi][ni][3] + by));
                }
            }
        }
    }
}

extern "C" void kernel_launch(void* const* d_in, const int* in_sizes, int n_in,
                              void* d_out, int out_size) {
    (void)in_sizes; (void)n_in; (void)out_size;
    const float* x    = (const float*)d_in[0];
    const float* Wg   = (const float*)d_in[1];
    const float* bg   = (const float*)d_in[2];
    const float* bias = (const float*)d_in[3];
    const float* W1   = (const float*)d_in[4];
    const float* b1   = (const float*)d_in[5];
    const float* W2   = (const float*)d_in[6];
    const float* b2   = (const float*)d_in[7];
    float* out = (float*)d_out;

    static int attr_done = 0;
    if (!attr_done) {
        cudaFuncSetAttribute(expert_mma<D_MODEL, EXPERT_DIM, 1, true>,
                             cudaFuncAttributeMaxDynamicSharedMemorySize, SM_TOTAL);
        cudaFuncSetAttribute(expert_mma<EXPERT_DIM, D_MODEL, 2, false>,
                             cudaFuncAttributeMaxDynamicSharedMemorySize, SM_TOTAL);
        attr_done = 1;
    }

    __half *w1h, *w2h;
    cudaGetSymbolAddress((void**)&w1h, g_W1h);
    cudaGetSymbolAddress((void**)&w2h, g_W2h);

    int n4  = NTOK * D_MODEL / 4;
    int n8x = NTOK * D_MODEL / 8;
    int n8w = NUM_EXPERTS * D_MODEL * EXPERT_DIM / 8;

    // launch order: FC1 is launch #4 (ncu profiles launch #4)
    prep_misc_kernel<<<(n4 + 255) / 256, 256>>>(x, (float4*)out, n4, n8x);       // 1
    gate_kernel<<<NTOK / 8, 256>>>(x, Wg, bg, bias);                             // 2
    prep_w_kernel<<<(n8w + 255) / 256, 256>>>(W1, W2, n8w);                      // 3
    expert_mma<D_MODEL, EXPERT_DIM, 1, true >                                    // 4 (profiled)
        <<<dim3(EXPERT_DIM / 256, NTOK / 128, NUM_EXPERTS), 512, SM_TOTAL>>>(w1h, b1, out);
    expert_mma<EXPERT_DIM, D_MODEL, 2, false>                                    // 5
        <<<dim3(D_MODEL / 256,  NTOK / 128, NUM_EXPERTS * 2), 512, SM_TOTAL>>>(w2h, b2, out);
}